// round 11
// baseline (speedup 1.0000x reference)
#include <cuda_runtime.h>
#include <cuda_fp16.h>

// DWHT (buggy torch in-place semantics) + channel shuffle, fully fused.
// x: (64, 256, 28, 28) f32  ->  out: (64, 512, 28, 28) f32
//
// 8 passes = (F o F)^4; G = F o F maps each aligned 16-channel chunk to a
// fixed signed output set. Channel shuffle (groups=8): ch->((ch&63)<<3)|(ch>>6),
// folded into closed-form affine output addresses (see stage 4).
//
// Round-10: R9 (fp16 smem storage / fp32 compute, zero-pad sparsity, CSE
// butterfly) + DOUBLE-BUFFERED smem (5 syncs -> 3) + affine-folded global
// store addressing (no runtime shuffle math) + streaming cache hints.

#define NPIX 32
#define HBUF (256 * 64)   // halves per buffer (512 ch pair-packed x 32 px) = 32KB

struct GOut {
    float4 Al;              // -> 4*jl + q
    float2 Bl, Dl, Gl;      // -> 128+2jl, 256+2jl, 384+2jl
    float  El;              // -> 320+jl
    float4 Ah, Ch, G4h;     // -> 4*jh+q, 128+4jh+q, 384+4jh+q
    float2 Bh, Dh, G2h, Fh; // -> 128+2jh, 256+2jh, 384+2jh, 320+2jh
    float  Eh;              // -> 320+jh
};

// CSE'd butterfly: s=pair sums, d=pair diffs, t/u=second-level sums/diffs.
__device__ __forceinline__ GOut compute_G(const float wl[16], const float wh[16]) {
    GOut o;
    float s[8], t[4], u[4];
#pragma unroll
    for (int i = 0; i < 8; i++) s[i] = wl[2*i] + wl[2*i+1];
#pragma unroll
    for (int q = 0; q < 4; q++) { t[q] = s[2*q] + s[2*q+1]; u[q] = s[2*q] - s[2*q+1]; }
    o.Al = make_float4(t[0], t[1], t[2], t[3]);
    o.Bl = make_float2(u[0] + u[1], u[2] + u[3]);
    o.Dl = make_float2(t[0] - t[1], t[2] - t[3]);
    o.Gl = make_float2(u[0] - u[1], u[2] - u[3]);
    o.El = o.Bl.x - o.Bl.y;

    float d[8];
#pragma unroll
    for (int i = 0; i < 8; i++) { s[i] = wh[2*i] + wh[2*i+1]; d[i] = wh[2*i] - wh[2*i+1]; }
#pragma unroll
    for (int q = 0; q < 4; q++) { t[q] = s[2*q] + s[2*q+1]; u[q] = s[2*q] - s[2*q+1]; }
    o.Ah  = make_float4(t[0], t[1], t[2], t[3]);
    o.Bh  = make_float2(u[0] + u[1], u[2] + u[3]);
    o.Dh  = make_float2(t[0] - t[1], t[2] - t[3]);
    o.G2h = make_float2(u[0] - u[1], u[2] - u[3]);
    o.Eh  = o.Bh.x - o.Bh.y;
    float c0 = d[0]+d[1], c1 = d[2]+d[3], c2 = d[4]+d[5], c3 = d[6]+d[7];
    o.Ch  = make_float4(c0, c1, c2, c3);
    o.G4h = make_float4(d[0]-d[1], d[2]-d[3], d[4]-d[5], d[6]-d[7]);
    o.Fh  = make_float2(c0 - c1, c2 - c3);
    return o;
}

__device__ __forceinline__ void zero16(float w[16]) {
#pragma unroll
    for (int m = 0; m < 16; m++) w[m] = 0.0f;
}

// Read one 16-channel chunk as 8 conflict-free half2 loads.
__device__ __forceinline__ void load_chunk(const __half* __restrict__ s, int chunk,
                                           int p, float w[16]) {
    const __half2* s2 = (const __half2*)s;
#pragma unroll
    for (int i = 0; i < 8; i++) {
        float2 v = __half22float2(s2[(8 * chunk + i) * 32 + p]);
        w[2*i] = v.x; w[2*i+1] = v.y;
    }
}

__device__ __forceinline__ void sts2(__half* __restrict__ s, int c, int p,
                                     float2 v) {                 // c even
    ((__half2*)s)[(c >> 1) * 32 + p] = __floats2half2_rn(v.x, v.y);
}
__device__ __forceinline__ void sts1(__half* __restrict__ s, int c, int p, float v) {
    s[(c >> 1) * 64 + 2 * p + (c & 1)] = __float2half_rn(v);
}

__device__ __forceinline__ void store_G(__half* __restrict__ s, int jl, int p,
                                        const GOut& o, bool skipAl, bool skipH4) {
    const int jh = jl + 16;
    if (!skipAl) {                        // targets in dead chunks 1,3 when skipped
        sts2(s, 4*jl,     p, make_float2(o.Al.x, o.Al.y));
        sts2(s, 4*jl + 2, p, make_float2(o.Al.z, o.Al.w));
    }
    sts2(s, 128 + 2*jl, p, o.Bl);
    sts2(s, 256 + 2*jl, p, o.Dl);
    sts2(s, 384 + 2*jl, p, o.Gl);
    sts1(s, 320 + jl, p, o.El);
    if (!skipH4) {                        // targets in dead chunks 7,15,31
        sts2(s, 4*jh,           p, make_float2(o.Ah.x, o.Ah.y));
        sts2(s, 4*jh + 2,       p, make_float2(o.Ah.z, o.Ah.w));
        sts2(s, 128 + 4*jh,     p, make_float2(o.Ch.x, o.Ch.y));
        sts2(s, 128 + 4*jh + 2, p, make_float2(o.Ch.z, o.Ch.w));
        sts2(s, 384 + 4*jh,     p, make_float2(o.G4h.x, o.G4h.y));
        sts2(s, 384 + 4*jh + 2, p, make_float2(o.G4h.z, o.G4h.w));
    }
    sts2(s, 128 + 2*jh, p, o.Bh);
    sts2(s, 256 + 2*jh, p, o.Dh);
    sts2(s, 384 + 2*jh, p, o.G2h);
    sts2(s, 320 + 2*jh, p, o.Fh);
    sts1(s, 320 + jh, p, o.Eh);
}

__global__ __launch_bounds__(512, 3)
void dwht_kernel(const float* __restrict__ x, float* __restrict__ out) {
    extern __shared__ __half sm[];      // two 32KB ping-pong buffers
    __half* buf0 = sm;
    __half* buf1 = sm + HBUF;

    const int tid = threadIdx.x;
    const int p   = tid & (NPIX - 1);   // pixel lane within warp [0,32)
    const int jl  = tid >> 5;           // chunk pair id = warp id [0,16)
    const int jh  = jl + 16;

    const int b    = blockIdx.x / 25;
    const int hw   = (blockIdx.x % 25) * NPIX + p;
    const bool valid = (hw < 784);
    const float* xp = x   + (size_t)b * (256 * 784) + hw;
    float*       op = out + (size_t)b * (512 * 784) + hw;

    float wl[16], wh[16];

    // ---- stage 1: global load; high 256 channels are the zero pad ----
#pragma unroll
    for (int m = 0; m < 16; m++)
        wl[m] = valid ? __ldcs(xp + (16 * jl + m) * 784) : 0.0f;
    zero16(wh);
    {
        GOut o = compute_G(wl, wh);     // high outputs fold to 0 and are DCE'd
        sts2(buf0, 4*jl,     p, make_float2(o.Al.x, o.Al.y));
        sts2(buf0, 4*jl + 2, p, make_float2(o.Al.z, o.Al.w));
        sts2(buf0, 128 + 2*jl, p, o.Bl);
        sts2(buf0, 256 + 2*jl, p, o.Dl);
        sts2(buf0, 384 + 2*jl, p, o.Gl);
        sts1(buf0, 320 + jl, p, o.El);
    }
    __syncthreads();

    // ---- stage 2: read buf0, write buf1 (no mid-stage sync needed) ----
    {
        const bool rl = (jl <= 3) | (jl == 8) | (jl == 9);
        const bool rh = (jl <= 1) | (jl == 4) | (jl == 8) | (jl == 9);
        if (rl) load_chunk(buf0, jl, p, wl); else zero16(wl);
        if (rh) load_chunk(buf0, jh, p, wh); else zero16(wh);
        GOut o = compute_G(wl, wh);
        // outputs landing in chunks {1,3,7,15,31} are exact zeros: skip stores
        const bool skipAl = ((jl >= 4) & (jl <= 7)) | (jl >= 12);
        const bool skipH4 = (jl >= 12);
        store_G(buf1, jl, p, o, skipAl, skipH4);
        __syncthreads();
    }

    // ---- stage 3: read buf1 (skip dead chunks {1,3,7,15,31}), write buf0 ----
    {
        const bool rl = !((jl == 1) | (jl == 3) | (jl == 7) | (jl == 15));
        const bool rh = (jl != 15);
        if (rl) load_chunk(buf1, jl, p, wl); else zero16(wl);
        if (rh) load_chunk(buf1, jh, p, wh); else zero16(wh);
        GOut o = compute_G(wl, wh);
        store_G(buf0, jl, p, o, false, false);
        __syncthreads();
    }

    // ---- stage 4: read buf0 -> shuffled global store (affine addresses) ----
    load_chunk(buf0, jl, p, wl);
    load_chunk(buf0, jh, p, wh);
    {
        GOut o = compute_G(wl, wh);
        if (valid) {
            // Shuffle c=((idx&63)<<3)|(idx>>6) solved per family:
            //   A:32jl+8q  Ah:+1  Ch:+3  G4h:+7   (base q32)
            //   Bl/Dl/Gl: 16jl+8r+{2,4,6}         (base q16)
            //   Bh/Dh/Fh/G2h: 256+16jl+8r+{2,4,5,6} (base q16h)
            //   El: 8jl+5   Eh: 8jl+133           (base qE)
            float* q32  = op + (size_t)(32 * jl) * 784;
            float* q16  = op + (size_t)(16 * jl) * 784;
            float* q16h = q16 + (size_t)256 * 784;
            float* qE   = op + (size_t)(8 * jl) * 784;
            __stcs(q32 + (size_t)( 0*8+0)*784, o.Al.x);
            __stcs(q32 + (size_t)( 1*8+0)*784, o.Al.y);
            __stcs(q32 + (size_t)( 2*8+0)*784, o.Al.z);
            __stcs(q32 + (size_t)( 3*8+0)*784, o.Al.w);
            __stcs(q32 + (size_t)( 0*8+1)*784, o.Ah.x);
            __stcs(q32 + (size_t)( 1*8+1)*784, o.Ah.y);
            __stcs(q32 + (size_t)( 2*8+1)*784, o.Ah.z);
            __stcs(q32 + (size_t)( 3*8+1)*784, o.Ah.w);
            __stcs(q32 + (size_t)( 0*8+3)*784, o.Ch.x);
            __stcs(q32 + (size_t)( 1*8+3)*784, o.Ch.y);
            __stcs(q32 + (size_t)( 2*8+3)*784, o.Ch.z);
            __stcs(q32 + (size_t)( 3*8+3)*784, o.Ch.w);
            __stcs(q32 + (size_t)( 0*8+7)*784, o.G4h.x);
            __stcs(q32 + (size_t)( 1*8+7)*784, o.G4h.y);
            __stcs(q32 + (size_t)( 2*8+7)*784, o.G4h.z);
            __stcs(q32 + (size_t)( 3*8+7)*784, o.G4h.w);
            __stcs(q16 + (size_t)(0*8+2)*784, o.Bl.x);
            __stcs(q16 + (size_t)(1*8+2)*784, o.Bl.y);
            __stcs(q16 + (size_t)(0*8+4)*784, o.Dl.x);
            __stcs(q16 + (size_t)(1*8+4)*784, o.Dl.y);
            __stcs(q16 + (size_t)(0*8+6)*784, o.Gl.x);
            __stcs(q16 + (size_t)(1*8+6)*784, o.Gl.y);
            __stcs(q16h + (size_t)(0*8+2)*784, o.Bh.x);
            __stcs(q16h + (size_t)(1*8+2)*784, o.Bh.y);
            __stcs(q16h + (size_t)(0*8+4)*784, o.Dh.x);
            __stcs(q16h + (size_t)(1*8+4)*784, o.Dh.y);
            __stcs(q16h + (size_t)(0*8+5)*784, o.Fh.x);
            __stcs(q16h + (size_t)(1*8+5)*784, o.Fh.y);
            __stcs(q16h + (size_t)(0*8+6)*784, o.G2h.x);
            __stcs(q16h + (size_t)(1*8+6)*784, o.G2h.y);
            __stcs(qE + (size_t)  5*784, o.El);
            __stcs(qE + (size_t)133*784, o.Eh);
        }
    }
}

extern "C" void kernel_launch(void* const* d_in, const int* in_sizes, int n_in,
                              void* d_out, int out_size) {
    const float* x = (const float*)d_in[0];
    float* out = (float*)d_out;
    const int smem = 2 * HBUF * sizeof(__half);   // 64 KB ping-pong
    static bool attr_set = false;                 // idempotent host-side attr
    if (!attr_set) {
        cudaFuncSetAttribute(dwht_kernel,
                             cudaFuncAttributeMaxDynamicSharedMemorySize, smem);
        attr_set = true;
    }
    // 64 images * 25 pixel-tiles of 32 (last tile predicated: 784 = 24*32+16)
    dwht_kernel<<<64 * 25, 512, smem>>>(x, out);
}